// round 2
// baseline (speedup 1.0000x reference)
#include <cuda_runtime.h>

// Problem constants
#define BB   16
#define HH   64
#define WWW  64
#define CIN  64
#define COUT 128
#define NS   8
#define NTOT (NS * COUT)   // 1024
#define NTAP 9

// Sampled weights, re-laid out as [tap][ci][s*128+co] : 9*64*1024 floats = 2.36 MB
__device__ float g_W[NTAP * CIN * NTOT];

// ---------------------------------------------------------------------------
// Kernel 1: sample weights  W[s,kh,kw,ci,co] = mu + noise * exp(logstd)
// and transpose into g_W[tap][ci][s*128+co]
// ---------------------------------------------------------------------------
__global__ void prep_kernel(const float* __restrict__ mu,
                            const float* __restrict__ logstd,
                            const float* __restrict__ noise) {
    int idx = blockIdx.x * blockDim.x + threadIdx.x;
    const int total = NS * NTAP * CIN * COUT;   // 589824
    if (idx >= total) return;
    int co  = idx & 127;
    int ci  = (idx >> 7) & 63;
    int tap = (idx >> 13) % NTAP;
    int s   = idx / (NTAP << 13);
    int mi  = (tap * CIN + ci) * COUT + co;     // mu/logstd index
    float w = mu[mi] + noise[idx] * expf(logstd[mi]);
    g_W[(tap * CIN + ci) * NTOT + s * COUT + co] = w;
}

// ---------------------------------------------------------------------------
// Packed-f32x2 helpers (Blackwell FFMA2: 2x scalar fp32 FMA throughput)
// ---------------------------------------------------------------------------
__device__ __forceinline__ unsigned long long pack2_dup(float v) {
    unsigned long long r;
    asm("mov.b64 %0, {%1, %2};" : "=l"(r) : "f"(v), "f"(v));
    return r;
}
__device__ __forceinline__ void ffma2(unsigned long long& d,
                                      unsigned long long a,
                                      unsigned long long b) {
    asm("fma.rn.f32x2 %0, %1, %2, %0;" : "+l"(d) : "l"(a), "l"(b));
}
__device__ __forceinline__ float2 unpack2(unsigned long long v) {
    float lo, hi;
    asm("mov.b64 {%0, %1}, %2;" : "=f"(lo), "=f"(hi) : "l"(v));
    return make_float2(lo, hi);
}

// ---------------------------------------------------------------------------
// Kernel 2: tiled conv + ELU.
// Block: 64 spatial (8x8 tile) x 128 cout (one sample). 256 threads.
// Thread: 4 m (one output row segment) x 8 n (couts tn*2 + 32*j + {0,1}).
// K-loop: 2 ci-chunks of 32, x patch staged per chunk, B staged per tap.
// ---------------------------------------------------------------------------
#define CCHUNK 32

__global__ __launch_bounds__(256, 2)
void conv_kernel(const float* __restrict__ x, float* __restrict__ out) {
    __shared__ float xs[CCHUNK * 100];    // [ci][p], p = py*10+px (10x10 patch)
    __shared__ float bs[CCHUNK * COUT];   // [ci][co]

    const int tid  = threadIdx.x;
    const int tile = blockIdx.x;          // 0..63 spatial tiles
    const int b    = blockIdx.y;          // 0..15
    const int nt   = blockIdx.z;          // 0..7 sample
    const int h0   = (tile >> 3) * 8;
    const int w0   = (tile & 7) * 8;

    const int tn  = tid & 15;             // cout group
    const int tm  = tid >> 4;             // 16 groups of 4 m (row-major)
    const int my  = tm >> 1;              // output row within tile
    const int mx0 = (tm & 1) * 4;         // col base (0 or 4)

    unsigned long long acc[4][4];
    #pragma unroll
    for (int i = 0; i < 4; i++)
        #pragma unroll
        for (int j = 0; j < 4; j++)
            acc[i][j] = 0ull;

    for (int cc = 0; cc < 2; cc++) {
        // ---- stage x patch chunk: xs[ci][p], ci = cc*32 .. +31 ----
        for (int lin = tid; lin < 800; lin += 256) {
            int p  = lin >> 3;
            int cg = lin & 7;             // 8 float4 groups cover 32 ci
            int py = p / 10, px = p % 10;
            int h = h0 - 1 + py, w = w0 - 1 + px;
            float4 v = make_float4(0.f, 0.f, 0.f, 0.f);
            if (h >= 0 && h < HH && w >= 0 && w < WWW) {
                v = *reinterpret_cast<const float4*>(
                    &x[(((b * HH + h) * WWW + w) * CIN) + cc * CCHUNK + cg * 4]);
            }
            xs[(cg * 4 + 0) * 100 + p] = v.x;
            xs[(cg * 4 + 1) * 100 + p] = v.y;
            xs[(cg * 4 + 2) * 100 + p] = v.z;
            xs[(cg * 4 + 3) * 100 + p] = v.w;
        }
        __syncthreads();

        for (int tap = 0; tap < NTAP; tap++) {
            // ---- stage B tile: bs[ci][co] = g_W[tap][cc*32+ci][nt*128+co] ----
            #pragma unroll
            for (int q = 0; q < 4; q++) {
                int lin = q * 256 + tid;
                int row = lin >> 5;        // ci within chunk
                int c4  = lin & 31;        // float4 index within 128 couts
                float4 v = *reinterpret_cast<const float4*>(
                    &g_W[(tap * CIN + cc * CCHUNK + row) * NTOT + nt * COUT + c4 * 4]);
                *reinterpret_cast<float4*>(&bs[row * COUT + c4 * 4]) = v;
            }
            __syncthreads();

            const int dy = tap / 3, dx = tap % 3;
            const int pbase = (my + dy) * 10 + mx0 + dx;

            #pragma unroll
            for (int ci = 0; ci < CCHUNK; ci++) {
                const float* xr = &xs[ci * 100 + pbase];
                unsigned long long av[4];
                #pragma unroll
                for (int i = 0; i < 4; i++) av[i] = pack2_dup(xr[i]);

                const unsigned long long* br =
                    reinterpret_cast<const unsigned long long*>(&bs[ci * COUT]);
                unsigned long long bv[4];
                #pragma unroll
                for (int j = 0; j < 4; j++) bv[j] = br[tn + 16 * j];

                #pragma unroll
                for (int i = 0; i < 4; i++)
                    #pragma unroll
                    for (int j = 0; j < 4; j++)
                        ffma2(acc[i][j], av[i], bv[j]);
            }
            __syncthreads();
        }
    }

    // ---- epilogue: ELU + store (couts tn*2 + 32*j + {0,1}) ----
    const int h = h0 + my;
    #pragma unroll
    for (int i = 0; i < 4; i++) {
        int w = w0 + mx0 + i;
        long long base = ((long long)((b * HH + h) * WWW + w)) * NTOT + nt * COUT;
        #pragma unroll
        for (int j = 0; j < 4; j++) {
            float2 v = unpack2(acc[i][j]);
            v.x = v.x > 0.f ? v.x : expm1f(v.x);
            v.y = v.y > 0.f ? v.y : expm1f(v.y);
            *reinterpret_cast<float2*>(&out[base + 32 * j + tn * 2]) = v;
        }
    }
}

// ---------------------------------------------------------------------------
extern "C" void kernel_launch(void* const* d_in, const int* in_sizes, int n_in,
                              void* d_out, int out_size) {
    const float* x      = (const float*)d_in[0];
    const float* mu     = (const float*)d_in[1];
    const float* logstd = (const float*)d_in[2];
    const float* noise  = (const float*)d_in[3];
    float* out = (float*)d_out;

    const int total_w = NS * NTAP * CIN * COUT;        // 589824
    prep_kernel<<<(total_w + 255) / 256, 256>>>(mu, logstd, noise);

    dim3 grid(64, BB, NS);   // spatial tiles, batch, sample
    conv_kernel<<<grid, 256>>>(x, out);
}

// round 4
// speedup vs baseline: 2.2839x; 2.2839x over previous
#include <cuda_runtime.h>
#include <cstdint>

// ---------------------------------------------------------------------------
// out[b,h,w,s,co] = ELU( conv3x3_SAME(x, W_s) ),  W_s = mu + n_s*exp(logstd)
// GEMM: C[65536,1024] = A_im2col[65536,576] * W[576,1024]; C row-major == out.
// Tensor path: legacy mma.sync m16n8k8 tf32 (sm_103 base target: no tcgen05).
// ---------------------------------------------------------------------------
#define NS    8
#define CINV  64
#define COUTV 128
#define NTOTV 1024
#define NTAP  9
#define ASTRIDE 68                      // padded row stride (floats): bank = lane
#define TILE_FLOATS (128 * ASTRIDE)     // 8704 floats = 34816 B
#define SMEM_TOTAL (4 * TILE_FLOATS * 4)  // A0,B0,A1,B1 = 139264 B

// Sampled weights tf32-rounded, layout [tap][n = s*128+co][ci]  (col-major KxN)
__device__ float g_W2[NTAP * NTOTV * CINV];
// x pre-rounded to tf32 (same NHWC layout)
__device__ float g_X[16 * 64 * 64 * CINV];

// ============================ helpers ======================================
__device__ __forceinline__ void cp_async16(uint32_t dst, const void* src) {
    asm volatile("cp.async.cg.shared.global [%0], [%1], 16;" :: "r"(dst), "l"(src));
}
__device__ __forceinline__ void cp_commit() { asm volatile("cp.async.commit_group;"); }
template <int N> __device__ __forceinline__ void cp_wait() {
    asm volatile("cp.async.wait_group %0;" :: "n"(N));
}
__device__ __forceinline__ uint32_t smem_u32(const void* p) {
    uint32_t a;
    asm("{ .reg .u64 t; cvta.to.shared.u64 t, %1; cvt.u32.u64 %0, t; }" : "=r"(a) : "l"(p));
    return a;
}
__device__ __forceinline__ void mma_tf32(float* c, const uint32_t* a, const uint32_t* b) {
    asm volatile(
        "mma.sync.aligned.m16n8k8.row.col.f32.tf32.tf32.f32 "
        "{%0,%1,%2,%3}, {%4,%5,%6,%7}, {%8,%9}, {%0,%1,%2,%3};"
        : "+f"(c[0]), "+f"(c[1]), "+f"(c[2]), "+f"(c[3])
        : "r"(a[0]), "r"(a[1]), "r"(a[2]), "r"(a[3]), "r"(b[0]), "r"(b[1]));
}
__device__ __forceinline__ float elu1(float v) { return v > 0.f ? v : expm1f(v); }
__device__ __forceinline__ float to_tf32(float v) {
    float r;
    asm("cvt.rna.tf32.f32 %0, %1;" : "=f"(r) : "f"(v));
    return r;
}

// ============================ prep kernels =================================
__global__ void prep_w(const float* __restrict__ mu,
                       const float* __restrict__ logstd,
                       const float* __restrict__ noise) {
    int idx = blockIdx.x * blockDim.x + threadIdx.x;
    const int total = NS * NTAP * CINV * COUTV;     // 589824
    if (idx >= total) return;
    int co  = idx & 127;
    int ci  = (idx >> 7) & 63;
    int tap = (idx >> 13) % NTAP;
    int s   = idx / (NTAP << 13);
    int mi  = (tap * CINV + ci) * COUTV + co;
    float w = mu[mi] + noise[idx] * expf(logstd[mi]);
    g_W2[(tap * NTOTV + s * COUTV + co) * CINV + ci] = to_tf32(w);
}

__global__ void prep_x(const float* __restrict__ x) {
    int idx = blockIdx.x * blockDim.x + threadIdx.x;   // 4194304 total
    g_X[idx] = to_tf32(x[idx]);
}

// ============================ conv kernel ==================================
// CTA: 128 (M) x 128 (N), 256 threads = 8 warps, warp tile 64x32 (wm=wid&1, wn=wid>>1).
// Per tap: A = shifted x patch [128 rows x 64 ci], B = W2 [128 n x 64 ci], both
// smem stride 68 floats. Double-buffered across taps with cp.async groups.

__device__ __forceinline__ void load_tap(uint32_t a_u32, uint32_t b_u32,
                                         int tap, int mtile, int ntile, int tid) {
    const int dy = tap / 3 - 1, dx = tap % 3 - 1;
    #pragma unroll
    for (int i = 0; i < 8; i++) {                     // A: 2048 float4s
        int lin = tid + (i << 8);
        int m = lin >> 4, c = lin & 15;
        int P = (mtile << 7) + m;
        int b = P >> 12, h = (P >> 6) & 63, w = P & 63;
        int hs = h + dy, ws = w + dx;
        uint32_t dst = a_u32 + (uint32_t)(m * ASTRIDE + c * 4) * 4u;
        if ((unsigned)hs < 64u && (unsigned)ws < 64u) {
            cp_async16(dst, g_X + ((((b << 6) + hs) << 6) + ws) * CINV + (c << 2));
        } else {
            asm volatile("st.shared.v4.b32 [%0], {%1,%1,%1,%1};" :: "r"(dst), "r"(0u) : "memory");
        }
    }
    const float* wb = g_W2 + (size_t)(tap * NTOTV + (ntile << 7)) * CINV;
    #pragma unroll
    for (int i = 0; i < 8; i++) {                     // B: 2048 float4s
        int lin = tid + (i << 8);
        int n = lin >> 4, c = lin & 15;
        cp_async16(b_u32 + (uint32_t)(n * ASTRIDE + c * 4) * 4u, wb + n * CINV + (c << 2));
    }
    cp_commit();
}

__global__ __launch_bounds__(256, 1)
void conv_mma_kernel(float* __restrict__ out) {
    extern __shared__ float smem[];
    float* bufA[2] = { smem,                   smem + 2 * TILE_FLOATS };
    float* bufB[2] = { smem + TILE_FLOATS,     smem + 3 * TILE_FLOATS };
    uint32_t uA[2] = { smem_u32(bufA[0]), smem_u32(bufA[1]) };
    uint32_t uB[2] = { smem_u32(bufB[0]), smem_u32(bufB[1]) };

    const int tid = threadIdx.x, wid = tid >> 5, lid = tid & 31;
    const int mtile = blockIdx.x, ntile = blockIdx.y;
    const int wm = wid & 1, wn = wid >> 1;            // warp tile (64m x 32n)
    const int l4 = lid >> 2, lm = lid & 3;

    float acc[4][4][4];
    #pragma unroll
    for (int i = 0; i < 4; i++)
        #pragma unroll
        for (int j = 0; j < 4; j++)
            #pragma unroll
            for (int k = 0; k < 4; k++) acc[i][j][k] = 0.f;

    load_tap(uA[0], uB[0], 0, mtile, ntile, tid);
    load_tap(uA[1], uB[1], 1, mtile, ntile, tid);

    #pragma unroll 1
    for (int tap = 0; tap < NTAP; tap++) {
        const int bs = tap & 1;
        cp_wait<1>();
        __syncthreads();

        const float* Aw = bufA[bs] + (wm * 64 + l4) * ASTRIDE + lm;
        const float* Bw = bufB[bs] + (wn * 32 + l4) * ASTRIDE + lm;

        #pragma unroll
        for (int kk = 0; kk < 8; kk++) {
            uint32_t a[4][4], b[4][2];
            #pragma unroll
            for (int mf = 0; mf < 4; mf++) {
                const float* p = Aw + mf * 16 * ASTRIDE + kk * 8;
                a[mf][0] = __float_as_uint(p[0]);
                a[mf][1] = __float_as_uint(p[8 * ASTRIDE]);
                a[mf][2] = __float_as_uint(p[4]);
                a[mf][3] = __float_as_uint(p[8 * ASTRIDE + 4]);
            }
            #pragma unroll
            for (int nf = 0; nf < 4; nf++) {
                const float* p = Bw + nf * 8 * ASTRIDE + kk * 8;
                b[nf][0] = __float_as_uint(p[0]);
                b[nf][1] = __float_as_uint(p[4]);
            }
            #pragma unroll
            for (int mf = 0; mf < 4; mf++)
                #pragma unroll
                for (int nf = 0; nf < 4; nf++)
                    mma_tf32(acc[mf][nf], a[mf], b[nf]);
        }

        if (tap + 2 <= 8) {
            __syncthreads();
            load_tap(uA[bs], uB[bs], tap + 2, mtile, ntile, tid);
        }
    }

    // ---- epilogue: ELU + float2 stores (C row-major == out) ----
    const int colb = (ntile << 7) + wn * 32 + lm * 2;
    #pragma unroll
    for (int mf = 0; mf < 4; mf++) {
        int row = (mtile << 7) + wm * 64 + mf * 16 + l4;
        float* o0 = out + (size_t)row * NTOTV + colb;
        float* o1 = o0 + 8 * NTOTV;                   // rows +8 for c2/c3
        #pragma unroll
        for (int nf = 0; nf < 4; nf++) {
            float2 v0, v1;
            v0.x = elu1(acc[mf][nf][0]); v0.y = elu1(acc[mf][nf][1]);
            v1.x = elu1(acc[mf][nf][2]); v1.y = elu1(acc[mf][nf][3]);
            *reinterpret_cast<float2*>(o0 + nf * 8) = v0;
            *reinterpret_cast<float2*>(o1 + nf * 8) = v1;
        }
    }
}

// ---------------------------------------------------------------------------
extern "C" void kernel_launch(void* const* d_in, const int* in_sizes, int n_in,
                              void* d_out, int out_size) {
    const float* x      = (const float*)d_in[0];
    const float* mu     = (const float*)d_in[1];
    const float* logstd = (const float*)d_in[2];
    const float* noise  = (const float*)d_in[3];
    float* out = (float*)d_out;

    prep_w<<<(NS * NTAP * CINV * COUTV + 255) / 256, 256>>>(mu, logstd, noise);
    prep_x<<<(16 * 64 * 64 * CINV) / 256, 256>>>(x);

    static int attr_set = 0;
    if (!attr_set) {
        cudaFuncSetAttribute(conv_mma_kernel,
                             cudaFuncAttributeMaxDynamicSharedMemorySize, SMEM_TOTAL);
        attr_set = 1;
    }
    dim3 grid(512, 8);   // 65536/128 m-tiles, 1024/128 n-tiles
    conv_mma_kernel<<<grid, 256, SMEM_TOTAL>>>(out);
}

// round 5
// speedup vs baseline: 5.9912x; 2.6233x over previous
#include <cuda_runtime.h>
#include <cuda_fp16.h>
#include <cstdint>

// ---------------------------------------------------------------------------
// out[b,h,w,s,co] = ELU( conv3x3_SAME(x, W_s) ),  W_s = mu + n_s*exp(logstd)
// GEMM: C[65536,1024] = A_im2col[65536,576] * W[576,1024]; C row-major == out.
// fp16 m16n8k16 HMMA (fp32 accum). fp16 mantissa == tf32 mantissa -> same accuracy.
// ---------------------------------------------------------------------------
#define NS    8
#define CINV  64
#define COUTV 128
#define NTOTV 1024
#define NTAP  9
#define PSTR  72                       // patch row stride (halfs): banks l4*4+lm
#define BSTR  72                       // B row stride (halfs)
#define PATCH_HALFS (264 * PSTR)       // 4 h-rows x 66 w
#define BSTAGE_HALFS (128 * BSTR)
#define SMEM_TOTAL ((PATCH_HALFS + 3 * BSTAGE_HALFS) * 2)   // 93312 B -> 2 CTA/SM

// fp16 inputs: x (NHWC) and sampled W [tap][n=s*128+co][ci]
__device__ __half g_Xh[16 * 64 * 64 * CINV];
__device__ __half g_Wh[NTAP * NTOTV * CINV];

// ============================ helpers ======================================
__device__ __forceinline__ void cp_async16(uint32_t dst, const void* src) {
    asm volatile("cp.async.cg.shared.global [%0], [%1], 16;" :: "r"(dst), "l"(src));
}
__device__ __forceinline__ void cp_commit() { asm volatile("cp.async.commit_group;"); }
template <int N> __device__ __forceinline__ void cp_wait() {
    asm volatile("cp.async.wait_group %0;" :: "n"(N));
}
__device__ __forceinline__ uint32_t smem_u32(const void* p) {
    uint32_t a;
    asm("{ .reg .u64 t; cvta.to.shared.u64 t, %1; cvt.u32.u64 %0, t; }" : "=r"(a) : "l"(p));
    return a;
}
__device__ __forceinline__ void mma_f16(float* c, const uint32_t* a, const uint32_t* b) {
    asm volatile(
        "mma.sync.aligned.m16n8k16.row.col.f32.f16.f16.f32 "
        "{%0,%1,%2,%3}, {%4,%5,%6,%7}, {%8,%9}, {%0,%1,%2,%3};"
        : "+f"(c[0]), "+f"(c[1]), "+f"(c[2]), "+f"(c[3])
        : "r"(a[0]), "r"(a[1]), "r"(a[2]), "r"(a[3]), "r"(b[0]), "r"(b[1]));
}
__device__ __forceinline__ float elu1(float v) { return v > 0.f ? v : expm1f(v); }
__device__ __forceinline__ uint32_t ldh2(const __half* p) {
    return *reinterpret_cast<const uint32_t*>(p);
}

// ============================ fused prep kernel ============================
// (2 launches per kernel_launch call => ncu -s 5 lands on the conv kernel)
__global__ void prep(const float* __restrict__ x,
                     const float* __restrict__ mu,
                     const float* __restrict__ logstd,
                     const float* __restrict__ noise) {
    int idx = blockIdx.x * blockDim.x + threadIdx.x;   // 4194304 threads
    g_Xh[idx] = __float2half_rn(x[idx]);
    if (idx < NS * NTAP * CINV * COUTV) {              // 589824
        int co  = idx & 127;
        int ci  = (idx >> 7) & 63;
        int tap = (idx >> 13) % NTAP;
        int s   = idx / (NTAP << 13);
        int mi  = (tap * CINV + ci) * COUTV + co;
        float w = mu[mi] + noise[idx] * expf(logstd[mi]);
        g_Wh[(tap * NTOTV + s * COUTV + co) * CINV + ci] = __float2half_rn(w);
    }
}

// ============================ conv kernel ==================================
// CTA: 128 M (= batch-fixed, 2 h-rows x 64 w) x 128 N. 256 thr, 8 warps 64x32.
// x halo patch loaded ONCE (taps = shifted views); B per-tap via 3-stage ring.

__device__ __forceinline__ void load_B(uint32_t b_u32, int tap, int ntile, int tid) {
    const __half* wb = g_Wh + (size_t)(tap * NTOTV + (ntile << 7)) * CINV;
    #pragma unroll
    for (int i = 0; i < 4; i++) {              // 1024 chunks of 8 halfs
        int lin = tid + (i << 8);
        int n = lin >> 3, c = lin & 7;
        cp_async16(b_u32 + (uint32_t)(n * BSTR + (c << 3)) * 2u, wb + n * CINV + (c << 3));
    }
    cp_commit();
}

__global__ __launch_bounds__(256, 2)
void conv_mma_kernel(float* __restrict__ out) {
    extern __shared__ __half smem[];
    __half* patch = smem;
    __half* bstg[3] = { smem + PATCH_HALFS,
                        smem + PATCH_HALFS + BSTAGE_HALFS,
                        smem + PATCH_HALFS + 2 * BSTAGE_HALFS };
    const uint32_t patch_u32 = smem_u32(patch);

    const int tid = threadIdx.x, wid = tid >> 5, lid = tid & 31;
    const int mtile = blockIdx.x, ntile = blockIdx.y;
    const int b  = mtile >> 5;                 // batch
    const int h0 = (mtile & 31) << 1;          // first of 2 h-rows
    const int wm = wid & 1, wn = wid >> 1;     // warp tile 64m x 32n
    const int l4 = lid >> 2, lm = lid & 3;

    // ---- prologue: patch (+B0) -> G0, B1 -> G1 ----
    {
        #pragma unroll
        for (int i = 0; i < 9; i++) {          // 2112 chunks of 8 halfs
            int lin = tid + (i << 8);
            if (lin >= 2112) break;
            int row = lin >> 3, c = lin & 7;   // row = hh*66+ww
            int hh = row / 66, ww = row % 66;
            int h = h0 - 1 + hh, w = ww - 1;
            uint32_t dst = patch_u32 + (uint32_t)(row * PSTR + (c << 3)) * 2u;
            if ((unsigned)h < 64u && (unsigned)w < 64u) {
                cp_async16(dst, g_Xh + (size_t)(((b << 6) + h) * 64 + w) * CINV + (c << 3));
            } else {
                asm volatile("st.shared.v4.b32 [%0], {%1,%1,%1,%1};" :: "r"(dst), "r"(0u) : "memory");
            }
        }
        load_B(smem_u32(bstg[0]), 0, ntile, tid);   // closes G0 (patch+B0)
        load_B(smem_u32(bstg[1]), 1, ntile, tid);   // G1
    }

    float acc[4][4][4];
    #pragma unroll
    for (int i = 0; i < 4; i++)
        #pragma unroll
        for (int j = 0; j < 4; j++)
            #pragma unroll
            for (int k = 0; k < 4; k++) acc[i][j][k] = 0.f;

    #pragma unroll 1
    for (int tap = 0; tap < NTAP; tap++) {
        if (tap == NTAP - 1) cp_wait<0>(); else cp_wait<1>();
        __syncthreads();
        if (tap + 2 < NTAP) load_B(smem_u32(bstg[(tap + 2) % 3]), tap + 2, ntile, tid);

        const int dy = tap / 3 - 1, dx = tap % 3 - 1;
        // A view base for this warp/tap: h-row = wm+dy+1, w = dx+1 + (frag col)
        const __half* Aw = patch + ((wm + dy + 1) * 66 + dx + 1 + l4) * PSTR + 2 * lm;
        const __half* Bw = bstg[tap % 3] + ((wn << 5) + l4) * BSTR + 2 * lm;

        #pragma unroll
        for (int kk = 0; kk < 4; kk++) {       // K = 4 x 16
            const int ko = kk << 4;
            uint32_t a[4][4], bb[4][2];
            #pragma unroll
            for (int mf = 0; mf < 4; mf++) {
                const __half* p = Aw + mf * (16 * PSTR) + ko;
                a[mf][0] = ldh2(p);
                a[mf][1] = ldh2(p + 8 * PSTR);
                a[mf][2] = ldh2(p + 8);
                a[mf][3] = ldh2(p + 8 * PSTR + 8);
            }
            #pragma unroll
            for (int nf = 0; nf < 4; nf++) {
                const __half* p = Bw + nf * (8 * BSTR) + ko;
                bb[nf][0] = ldh2(p);
                bb[nf][1] = ldh2(p + 8);
            }
            #pragma unroll
            for (int mf = 0; mf < 4; mf++)
                #pragma unroll
                for (int nf = 0; nf < 4; nf++)
                    mma_f16(acc[mf][nf], a[mf], bb[nf]);
        }
    }

    // ---- epilogue: ELU + float2 stores (C row-major == out) ----
    const int colb = (ntile << 7) + (wn << 5) + lm * 2;
    #pragma unroll
    for (int mf = 0; mf < 4; mf++) {
        int row = (mtile << 7) + wm * 64 + mf * 16 + l4;
        float* o0 = out + (size_t)row * NTOTV + colb;
        float* o1 = o0 + 8 * NTOTV;
        #pragma unroll
        for (int nf = 0; nf < 4; nf++) {
            float2 v0, v1;
            v0.x = elu1(acc[mf][nf][0]); v0.y = elu1(acc[mf][nf][1]);
            v1.x = elu1(acc[mf][nf][2]); v1.y = elu1(acc[mf][nf][3]);
            *reinterpret_cast<float2*>(o0 + nf * 8) = v0;
            *reinterpret_cast<float2*>(o1 + nf * 8) = v1;
        }
    }
}

// ---------------------------------------------------------------------------
extern "C" void kernel_launch(void* const* d_in, const int* in_sizes, int n_in,
                              void* d_out, int out_size) {
    const float* x      = (const float*)d_in[0];
    const float* mu     = (const float*)d_in[1];
    const float* logstd = (const float*)d_in[2];
    const float* noise  = (const float*)d_in[3];
    float* out = (float*)d_out;

    prep<<<(16 * 64 * 64 * CINV) / 256, 256>>>(x, mu, logstd, noise);

    cudaFuncSetAttribute(conv_mma_kernel,
                         cudaFuncAttributeMaxDynamicSharedMemorySize, SMEM_TOTAL);
    dim3 grid(512, 8);   // 65536/128 m-tiles, 1024/128 n-tiles
    conv_mma_kernel<<<grid, 256, SMEM_TOTAL>>>(out);
}

// round 6
// speedup vs baseline: 6.5754x; 1.0975x over previous
#include <cuda_runtime.h>
#include <cuda_fp16.h>
#include <cstdint>

// ---------------------------------------------------------------------------
// out[b,h,w,s,co] = ELU( conv3x3_SAME(x, W_s) ),  W_s = mu + n_s*exp(logstd)
// GEMM: C[65536,1024] = A_im2col[65536,576] * W[576,1024]; C row-major == out.
// fp16 m16n8k16 HMMA (fp32 accum), fragments via ldmatrix (LDSM).
// ---------------------------------------------------------------------------
#define NS    8
#define CINV  64
#define COUTV 128
#define NTOTV 1024
#define NTAP  9
#define PSTR  72                       // patch row stride (halfs)
#define BSTR  72                       // B row stride (halfs)
#define PATCH_HALFS (264 * PSTR)       // 4 h-rows x 66 w
#define BSTAGE_HALFS (128 * BSTR)
#define SMEM_TOTAL ((PATCH_HALFS + 3 * BSTAGE_HALFS) * 2)   // 93312 B -> 2 CTA/SM

__device__ __half g_Xh[16 * 64 * 64 * CINV];
__device__ __half g_Wh[NTAP * NTOTV * CINV];

// ============================ helpers ======================================
__device__ __forceinline__ void cp_async16(uint32_t dst, const void* src) {
    asm volatile("cp.async.cg.shared.global [%0], [%1], 16;" :: "r"(dst), "l"(src));
}
__device__ __forceinline__ void cp_commit() { asm volatile("cp.async.commit_group;"); }
template <int N> __device__ __forceinline__ void cp_wait() {
    asm volatile("cp.async.wait_group %0;" :: "n"(N));
}
__device__ __forceinline__ uint32_t smem_u32(const void* p) {
    uint32_t a;
    asm("{ .reg .u64 t; cvta.to.shared.u64 t, %1; cvt.u32.u64 %0, t; }" : "=r"(a) : "l"(p));
    return a;
}
__device__ __forceinline__ void ldsm4(uint32_t& r0, uint32_t& r1, uint32_t& r2,
                                      uint32_t& r3, uint32_t addr) {
    asm volatile("ldmatrix.sync.aligned.m8n8.x4.shared.b16 {%0,%1,%2,%3}, [%4];"
                 : "=r"(r0), "=r"(r1), "=r"(r2), "=r"(r3) : "r"(addr));
}
__device__ __forceinline__ void mma_f16(float* c, const uint32_t* a, const uint32_t* b) {
    asm volatile(
        "mma.sync.aligned.m16n8k16.row.col.f32.f16.f16.f32 "
        "{%0,%1,%2,%3}, {%4,%5,%6,%7}, {%8,%9}, {%0,%1,%2,%3};"
        : "+f"(c[0]), "+f"(c[1]), "+f"(c[2]), "+f"(c[3])
        : "r"(a[0]), "r"(a[1]), "r"(a[2]), "r"(a[3]), "r"(b[0]), "r"(b[1]));
}
__device__ __forceinline__ float elu1(float v) { return v > 0.f ? v : expm1f(v); }

// ============================ fused prep kernel ============================
__global__ void prep(const float* __restrict__ x,
                     const float* __restrict__ mu,
                     const float* __restrict__ logstd,
                     const float* __restrict__ noise) {
    int idx = blockIdx.x * blockDim.x + threadIdx.x;   // 4194304 threads
    g_Xh[idx] = __float2half_rn(x[idx]);
    if (idx < NS * NTAP * CINV * COUTV) {
        int co  = idx & 127;
        int ci  = (idx >> 7) & 63;
        int tap = (idx >> 13) % NTAP;
        int s   = idx / (NTAP << 13);
        int mi  = (tap * CINV + ci) * COUTV + co;
        float w = mu[mi] + noise[idx] * expf(logstd[mi]);
        g_Wh[(tap * NTOTV + s * COUTV + co) * CINV + ci] = __float2half_rn(w);
    }
}

// ============================ conv kernel ==================================
// CTA: 128 M (batch-fixed, 2 h-rows x 64 w) x 128 N. 256 thr, 8 warps 64x32.
// x halo patch loaded ONCE; B per-tap via 3-stage cp.async ring; LDSM frags.

__device__ __forceinline__ void load_B(uint32_t b_u32, int tap, int ntile, int tid) {
    const __half* wb = g_Wh + (size_t)(tap * NTOTV + (ntile << 7)) * CINV;
    #pragma unroll
    for (int i = 0; i < 4; i++) {
        int lin = tid + (i << 8);
        int n = lin >> 3, c = lin & 7;
        cp_async16(b_u32 + (uint32_t)(n * BSTR + (c << 3)) * 2u, wb + n * CINV + (c << 3));
    }
    cp_commit();
}

__global__ __launch_bounds__(256, 2)
void conv_mma_kernel(float* __restrict__ out) {
    extern __shared__ __half smem[];
    __half* patch = smem;
    const uint32_t patch_u32 = smem_u32(patch);
    const uint32_t bu[3] = { patch_u32 + PATCH_HALFS * 2u,
                             patch_u32 + (PATCH_HALFS + BSTAGE_HALFS) * 2u,
                             patch_u32 + (PATCH_HALFS + 2 * BSTAGE_HALFS) * 2u };

    const int tid = threadIdx.x, wid = tid >> 5, lid = tid & 31;
    const int mtile = blockIdx.x, ntile = blockIdx.y;
    const int b  = mtile >> 5;
    const int h0 = (mtile & 31) << 1;
    const int wm = wid & 1, wn = wid >> 1;     // warp tile 64m x 32n

    // ldmatrix per-lane offsets (bytes)
    const uint32_t a_lane = (uint32_t)((lid & 15) * PSTR + (lid >> 4) * 8) * 2u;
    const uint32_t b_lane = (uint32_t)((((lid & 7) + ((lid >> 4) << 3)) * BSTR)
                                       + (((lid >> 3) & 1) << 3)) * 2u;

    // ---- prologue: patch -> G0 (with B0), B1 -> G1 ----
    {
        #pragma unroll
        for (int i = 0; i < 9; i++) {          // 2112 chunks of 8 halfs
            int lin = tid + (i << 8);
            if (lin >= 2112) break;
            int row = lin >> 3, c = lin & 7;   // row = hh*66+ww
            int hh = row / 66, ww = row % 66;
            int h = h0 - 1 + hh, w = ww - 1;
            uint32_t dst = patch_u32 + (uint32_t)(row * PSTR + (c << 3)) * 2u;
            if ((unsigned)h < 64u && (unsigned)w < 64u) {
                cp_async16(dst, g_Xh + (size_t)(((b << 6) + h) * 64 + w) * CINV + (c << 3));
            } else {
                asm volatile("st.shared.v4.b32 [%0], {%1,%1,%1,%1};" :: "r"(dst), "r"(0u) : "memory");
            }
        }
        load_B(bu[0], 0, ntile, tid);
        load_B(bu[1], 1, ntile, tid);
    }

    float acc[4][4][4];
    #pragma unroll
    for (int i = 0; i < 4; i++)
        #pragma unroll
        for (int j = 0; j < 4; j++)
            #pragma unroll
            for (int k = 0; k < 4; k++) acc[i][j][k] = 0.f;

    const uint32_t b_warp = (uint32_t)((wn << 5) * BSTR) * 2u + b_lane;

    #pragma unroll 1
    for (int tap = 0; tap < NTAP; tap++) {
        if (tap == NTAP - 1) cp_wait<0>(); else cp_wait<1>();
        __syncthreads();
        if (tap + 2 < NTAP) load_B(bu[(tap + 2) % 3], tap + 2, ntile, tid);

        const int dy = tap / 3 - 1, dx = tap % 3 - 1;
        const uint32_t aBase = patch_u32
            + (uint32_t)(((wm + dy + 1) * 66 + dx + 1) * PSTR) * 2u + a_lane;
        const uint32_t bBase = bu[tap % 3] + b_warp;

        #pragma unroll
        for (int kk = 0; kk < 4; kk++) {
            uint32_t a[4][4], bb[4][2];
            #pragma unroll
            for (int mf = 0; mf < 4; mf++)
                ldsm4(a[mf][0], a[mf][1], a[mf][2], a[mf][3],
                      aBase + (uint32_t)(mf * 16 * PSTR + kk * 16) * 2u);
            #pragma unroll
            for (int np = 0; np < 2; np++)
                ldsm4(bb[2 * np][0], bb[2 * np][1], bb[2 * np + 1][0], bb[2 * np + 1][1],
                      bBase + (uint32_t)(np * 16 * BSTR + kk * 16) * 2u);
            #pragma unroll
            for (int mf = 0; mf < 4; mf++)
                #pragma unroll
                for (int nf = 0; nf < 4; nf++)
                    mma_f16(acc[mf][nf], a[mf], bb[nf]);
        }
    }

    // ---- epilogue: ELU + float2 stores ----
    const int l4 = lid >> 2, lm = lid & 3;
    const int colb = (ntile << 7) + (wn << 5) + lm * 2;
    #pragma unroll
    for (int mf = 0; mf < 4; mf++) {
        int row = (mtile << 7) + wm * 64 + mf * 16 + l4;
        float* o0 = out + (size_t)row * NTOTV + colb;
        float* o1 = o0 + 8 * NTOTV;
        #pragma unroll
        for (int nf = 0; nf < 4; nf++) {
            float2 v0, v1;
            v0.x = elu1(acc[mf][nf][0]); v0.y = elu1(acc[mf][nf][1]);
            v1.x = elu1(acc[mf][nf][2]); v1.y = elu1(acc[mf][nf][3]);
            *reinterpret_cast<float2*>(o0 + nf * 8) = v0;
            *reinterpret_cast<float2*>(o1 + nf * 8) = v1;
        }
    }
}

// ---------------------------------------------------------------------------
extern "C" void kernel_launch(void* const* d_in, const int* in_sizes, int n_in,
                              void* d_out, int out_size) {
    const float* x      = (const float*)d_in[0];
    const float* mu     = (const float*)d_in[1];
    const float* logstd = (const float*)d_in[2];
    const float* noise  = (const float*)d_in[3];
    float* out = (float*)d_out;

    prep<<<(16 * 64 * 64 * CINV) / 256, 256>>>(x, mu, logstd, noise);

    cudaFuncSetAttribute(conv_mma_kernel,
                         cudaFuncAttributeMaxDynamicSharedMemorySize, SMEM_TOTAL);
    dim3 grid(512, 8);   // 65536/128 m-tiles, 1024/128 n-tiles
    conv_mma_kernel<<<grid, 256, SMEM_TOTAL>>>(out);
}

// round 7
// speedup vs baseline: 6.9484x; 1.0567x over previous
#include <cuda_runtime.h>
#include <cuda_fp16.h>
#include <cstdint>

// ---------------------------------------------------------------------------
// out[b,h,w,s,co] = ELU( conv3x3_SAME(x, W_s) ),  W_s = mu + n_s*exp(logstd)
// GEMM: C[65536,1024] = A_im2col[65536,576] * W[576,1024]; C row-major == out.
// fp16 m16n8k16 HMMA + LDSM, register-fragment software pipeline so the
// smem port and tensor pipe overlap (they were serializing: 50%+55% additive).
// ---------------------------------------------------------------------------
#define NS    8
#define CINV  64
#define COUTV 128
#define NTOTV 1024
#define NTAP  9
#define PSTR  72
#define BSTR  72
#define PATCH_HALFS (264 * PSTR)            // 4 h-rows x 66 w
#define BSTAGE_HALFS (128 * BSTR)
#define NSTAGE 4
#define SMEM_TOTAL ((PATCH_HALFS + NSTAGE * BSTAGE_HALFS) * 2)   // 111744 B -> 2 CTA/SM

__device__ __half g_Xh[16 * 64 * 64 * CINV];
__device__ __half g_Wh[NTAP * NTOTV * CINV];

// ============================ helpers ======================================
__device__ __forceinline__ void cp_async16(uint32_t dst, const void* src) {
    asm volatile("cp.async.cg.shared.global [%0], [%1], 16;" :: "r"(dst), "l"(src));
}
__device__ __forceinline__ void cp_commit() { asm volatile("cp.async.commit_group;"); }
template <int N> __device__ __forceinline__ void cp_wait() {
    asm volatile("cp.async.wait_group %0;" :: "n"(N));
}
__device__ __forceinline__ uint32_t smem_u32(const void* p) {
    uint32_t a;
    asm("{ .reg .u64 t; cvta.to.shared.u64 t, %1; cvt.u32.u64 %0, t; }" : "=r"(a) : "l"(p));
    return a;
}
__device__ __forceinline__ void ldsm4(uint32_t& r0, uint32_t& r1, uint32_t& r2,
                                      uint32_t& r3, uint32_t addr) {
    asm volatile("ldmatrix.sync.aligned.m8n8.x4.shared.b16 {%0,%1,%2,%3}, [%4];"
                 : "=r"(r0), "=r"(r1), "=r"(r2), "=r"(r3) : "r"(addr));
}
__device__ __forceinline__ void mma_f16(float* c, const uint32_t* a, const uint32_t* b) {
    asm volatile(
        "mma.sync.aligned.m16n8k16.row.col.f32.f16.f16.f32 "
        "{%0,%1,%2,%3}, {%4,%5,%6,%7}, {%8,%9}, {%0,%1,%2,%3};"
        : "+f"(c[0]), "+f"(c[1]), "+f"(c[2]), "+f"(c[3])
        : "r"(a[0]), "r"(a[1]), "r"(a[2]), "r"(a[3]), "r"(b[0]), "r"(b[1]));
}
__device__ __forceinline__ float elu1(float v) { return v > 0.f ? v : expm1f(v); }

struct Frags { uint32_t a[4][4]; uint32_t b[4][2]; };

// ============================ fused prep kernel ============================
__global__ void prep(const float* __restrict__ x,
                     const float* __restrict__ mu,
                     const float* __restrict__ logstd,
                     const float* __restrict__ noise) {
    int idx = blockIdx.x * blockDim.x + threadIdx.x;      // 1048576 threads
    float4 v = reinterpret_cast<const float4*>(x)[idx];
    __half2* xo = reinterpret_cast<__half2*>(g_Xh) + idx * 2;
    xo[0] = __floats2half2_rn(v.x, v.y);
    xo[1] = __floats2half2_rn(v.z, v.w);
    if (idx < NS * NTAP * CINV * COUTV) {                 // 589824
        int co  = idx & 127;
        int ci  = (idx >> 7) & 63;
        int tap = (idx >> 13) % NTAP;
        int s   = idx / (NTAP << 13);
        int mi  = (tap * CINV + ci) * COUTV + co;
        float w = mu[mi] + noise[idx] * expf(logstd[mi]);
        g_Wh[(tap * NTOTV + s * COUTV + co) * CINV + ci] = __float2half_rn(w);
    }
}

// ============================ conv kernel ==================================
__device__ __forceinline__ void load_B(uint32_t b_u32, int tap, int ntile, int tid) {
    const __half* wb = g_Wh + (size_t)(tap * NTOTV + (ntile << 7)) * CINV;
    #pragma unroll
    for (int i = 0; i < 4; i++) {
        int lin = tid + (i << 8);
        int n = lin >> 3, c = lin & 7;
        cp_async16(b_u32 + (uint32_t)(n * BSTR + (c << 3)) * 2u, wb + n * CINV + (c << 3));
    }
    cp_commit();
}

__device__ __forceinline__ void load_frags(Frags& F, int tap, int kk,
                                           uint32_t pA0, uint32_t bu0, uint32_t b_warp) {
    const int dy = tap / 3 - 1, dx = tap % 3 - 1;
    const uint32_t aBase = pA0 + (uint32_t)((dy * 66 + dx) * PSTR * 2) + (uint32_t)(kk * 32);
    const uint32_t bBase = bu0 + (uint32_t)((tap & 3) * (BSTAGE_HALFS * 2)) + b_warp
                         + (uint32_t)(kk * 32);
    #pragma unroll
    for (int mf = 0; mf < 4; mf++)
        ldsm4(F.a[mf][0], F.a[mf][1], F.a[mf][2], F.a[mf][3],
              aBase + (uint32_t)(mf * 16 * PSTR * 2));
    #pragma unroll
    for (int np = 0; np < 2; np++)
        ldsm4(F.b[2 * np][0], F.b[2 * np][1], F.b[2 * np + 1][0], F.b[2 * np + 1][1],
              bBase + (uint32_t)(np * 16 * BSTR * 2));
}

__global__ __launch_bounds__(256, 2)
void conv_mma_kernel(float* __restrict__ out) {
    extern __shared__ __half smem[];
    const uint32_t patch_u32 = smem_u32(smem);
    const uint32_t bu0 = patch_u32 + PATCH_HALFS * 2u;

    const int tid = threadIdx.x, wid = tid >> 5, lid = tid & 31;
    const int mtile = blockIdx.x, ntile = blockIdx.y;
    const int b  = mtile >> 5;
    const int h0 = (mtile & 31) << 1;
    const int wm = wid & 1, wn = wid >> 1;

    const uint32_t a_lane = (uint32_t)((lid & 15) * PSTR + (lid >> 4) * 8) * 2u;
    const uint32_t b_lane = (uint32_t)((((lid & 7) + ((lid >> 4) << 3)) * BSTR)
                                       + (((lid >> 3) & 1) << 3)) * 2u;
    const uint32_t pA0    = patch_u32 + (uint32_t)(((wm + 1) * 66 + 1) * PSTR * 2) + a_lane;
    const uint32_t b_warp = (uint32_t)((wn << 5) * BSTR) * 2u + b_lane;

    // ---- prologue: G0 = patch + B(tap0), G1 = B1, G2 = B2 ----
    #pragma unroll
    for (int i = 0; i < 9; i++) {
        int lin = tid + (i << 8);
        if (lin >= 2112) break;
        int row = lin >> 3, c = lin & 7;
        int hh = row / 66, ww = row % 66;
        int h = h0 - 1 + hh, w = ww - 1;
        uint32_t dst = patch_u32 + (uint32_t)(row * PSTR + (c << 3)) * 2u;
        if ((unsigned)h < 64u && (unsigned)w < 64u) {
            cp_async16(dst, g_Xh + (size_t)(((b << 6) + h) * 64 + w) * CINV + (c << 3));
        } else {
            asm volatile("st.shared.v4.b32 [%0], {%1,%1,%1,%1};" :: "r"(dst), "r"(0u) : "memory");
        }
    }
    load_B(bu0, 0, ntile, tid);                       // closes G0
    load_B(bu0 + BSTAGE_HALFS * 2u, 1, ntile, tid);   // G1
    load_B(bu0 + 2u * BSTAGE_HALFS * 2u, 2, ntile, tid); // G2

    float acc[4][4][4];
    #pragma unroll
    for (int i = 0; i < 4; i++)
        #pragma unroll
        for (int j = 0; j < 4; j++)
            #pragma unroll
            for (int k = 0; k < 4; k++) acc[i][j][k] = 0.f;

    cp_wait<1>();              // G0,G1 done -> taps 0 and 1 readable
    __syncthreads();

    Frags f[2];
    load_frags(f[0], 0, 0, pA0, bu0, b_warp);

    #pragma unroll 1
    for (int tap = 0; tap < NTAP; tap++) {
        if (tap >= 1) {
            if (tap < 6) cp_wait<1>(); else cp_wait<0>();
            __syncthreads();
        }
        if (tap + 3 <= 8)
            load_B(bu0 + (uint32_t)(((tap + 3) & 3) * (BSTAGE_HALFS * 2)), tap + 3, ntile, tid);

        #pragma unroll
        for (int kk = 0; kk < 4; kk++) {
            Frags& c = f[kk & 1];
            Frags& n = f[(kk & 1) ^ 1];
            if (kk < 3)          load_frags(n, tap, kk + 1, pA0, bu0, b_warp);
            else if (tap < 8)    load_frags(n, tap + 1, 0, pA0, bu0, b_warp);
            #pragma unroll
            for (int mf = 0; mf < 4; mf++)
                #pragma unroll
                for (int nf = 0; nf < 4; nf++)
                    mma_f16(acc[mf][nf], c.a[mf], c.b[nf]);
        }
    }

    // ---- epilogue: ELU + float2 stores ----
    const int l4 = lid >> 2, lm = lid & 3;
    const int colb = (ntile << 7) + (wn << 5) + lm * 2;
    #pragma unroll
    for (int mf = 0; mf < 4; mf++) {
        int row = (mtile << 7) + wm * 64 + mf * 16 + l4;
        float* o0 = out + (size_t)row * NTOTV + colb;
        float* o1 = o0 + 8 * NTOTV;
        #pragma unroll
        for (int nf = 0; nf < 4; nf++) {
            float2 v0, v1;
            v0.x = elu1(acc[mf][nf][0]); v0.y = elu1(acc[mf][nf][1]);
            v1.x = elu1(acc[mf][nf][2]); v1.y = elu1(acc[mf][nf][3]);
            *reinterpret_cast<float2*>(o0 + nf * 8) = v0;
            *reinterpret_cast<float2*>(o1 + nf * 8) = v1;
        }
    }
}

// ---------------------------------------------------------------------------
extern "C" void kernel_launch(void* const* d_in, const int* in_sizes, int n_in,
                              void* d_out, int out_size) {
    const float* x      = (const float*)d_in[0];
    const float* mu     = (const float*)d_in[1];
    const float* logstd = (const float*)d_in[2];
    const float* noise  = (const float*)d_in[3];
    float* out = (float*)d_out;

    prep<<<4096, 256>>>(x, mu, logstd, noise);

    cudaFuncSetAttribute(conv_mma_kernel,
                         cudaFuncAttributeMaxDynamicSharedMemorySize, SMEM_TOTAL);
    dim3 grid(512, 8);
    conv_mma_kernel<<<grid, 256, SMEM_TOTAL>>>(out);
}